// round 16
// baseline (speedup 1.0000x reference)
#include <cuda_runtime.h>
#include <math.h>
#include <stdint.h>

#define DMODEL 1024
#define NH     16
#define DEPTH  64
#define BATCH  2
#define SEQ    2048
#define MROWS  (BATCH*SEQ)   // 4096
#define NT     (SEQ/32)      // 64 kv chunks

// Scratch (allocation-free rule: __device__ globals)
__device__ float g_Qh[BATCH*NH*SEQ*DEPTH];
__device__ float g_Kh[BATCH*NH*SEQ*DEPTH];
__device__ float g_VhT[BATCH*NH*DEPTH*SEQ];   // V transposed: [b,h,d,s]
__device__ float g_Oc[MROWS*DMODEL];
// tf32-pre-rounded operand copies
__device__ float g_Qr[MROWS*DMODEL];
__device__ float g_Kr[MROWS*DMODEL];
__device__ float g_Vr[MROWS*DMODEL];
__device__ float g_Wq[DMODEL*DMODEL];
__device__ float g_Wk[DMODEL*DMODEL];
__device__ float g_Wv[DMODEL*DMODEL];
__device__ float g_Wo[DMODEL*DMODEL];

__device__ __forceinline__ float to_tf32(float x) {
    float r;
    asm("cvt.rna.tf32.f32 %0, %1;" : "=f"(r) : "f"(x));
    return r;
}
__device__ __forceinline__ float4 cvt4(float4 v) {
    return make_float4(to_tf32(v.x), to_tf32(v.y), to_tf32(v.z), to_tf32(v.w));
}

__device__ __forceinline__ void mma8(float c[4], const uint32_t a[4], const uint32_t b[2]) {
    asm volatile(
        "mma.sync.aligned.m16n8k8.row.col.f32.tf32.tf32.f32 "
        "{%0,%1,%2,%3},{%4,%5,%6,%7},{%8,%9},{%0,%1,%2,%3};\n"
        : "+f"(c[0]), "+f"(c[1]), "+f"(c[2]), "+f"(c[3])
        : "r"(a[0]), "r"(a[1]), "r"(a[2]), "r"(a[3]), "r"(b[0]), "r"(b[1]));
}

__device__ __forceinline__ void ldsm4(uint32_t* r, uint32_t addr) {
    asm volatile("ldmatrix.sync.aligned.m8n8.x4.shared.b16 {%0,%1,%2,%3}, [%4];"
                 : "=r"(r[0]), "=r"(r[1]), "=r"(r[2]), "=r"(r[3]) : "r"(addr));
}

__device__ __forceinline__ void cpasync16(uint32_t dst, const void* src) {
    asm volatile("cp.async.ca.shared.global [%0], [%1], 16;\n" :: "r"(dst), "l"(src));
}
__device__ __forceinline__ void cp_commit() {
    asm volatile("cp.async.commit_group;\n");
}
template<int N>
__device__ __forceinline__ void cp_wait() {
    asm volatile("cp.async.wait_group %0;\n" :: "n"(N));
}

// ---------------------------------------------------------------------------
// One-time tf32 rounding of q,k,v (1M float4 each) + 4 weights (256K each).
// ---------------------------------------------------------------------------
__global__ __launch_bounds__(256)
void prep_round(const float4* __restrict__ q, const float4* __restrict__ k,
                const float4* __restrict__ v,
                const float4* __restrict__ wq, const float4* __restrict__ wk,
                const float4* __restrict__ wv, const float4* __restrict__ wo,
                float4* __restrict__ qr, float4* __restrict__ kr,
                float4* __restrict__ vr,
                float4* __restrict__ wqr, float4* __restrict__ wkr,
                float4* __restrict__ wvr, float4* __restrict__ wor)
{
    const int NB = MROWS*DMODEL/4;    // 1048576
    const int NW = DMODEL*DMODEL/4;   // 262144
    int i = blockIdx.x * 256 + threadIdx.x;
    const float4* src;
    float4* dst;
    int off;
    if (i < 3*NB) {
        const int s = i >> 20;         // /NB
        off = i & (NB - 1);
        src = (s == 0) ? q : (s == 1) ? k : v;
        dst = (s == 0) ? qr : (s == 1) ? kr : vr;
    } else {
        const int j = i - 3*NB;
        const int s = j >> 18;         // /NW
        off = j & (NW - 1);
        src = (s == 0) ? wq : (s == 1) ? wk : (s == 2) ? wv : wo;
        dst = (s == 0) ? wqr : (s == 1) ? wkr : (s == 2) ? wvr : wor;
    }
    dst[off] = cvt4(src[off]);
}

// ---------------------------------------------------------------------------
// C = A[4096,1024] @ W[1024,1024]^T + bias, tf32 tensor-core GEMM.
// All operands PRE-ROUNDED to tf32 in global (zero cvt in hot loop).
// 128x128 tile, BK=16, cp.async 3-stage pipeline, ONE sync per iter.
// Dynamic smem: 3 stages x (As 10240B + Ws 10240B) = 61440 B.
// QKV=true: fused projections via blockIdx.z; z==2 writes V transposed.
// SPLIT outputs stored tf32-rounded for the attention kernel.
// ---------------------------------------------------------------------------
template<bool SPLIT, bool QKV>
__global__ __launch_bounds__(256)
void gemm_tc(const float* __restrict__ A0, const float* __restrict__ W0,
             const float* __restrict__ b0, float* __restrict__ C0,
             const float* __restrict__ A1, const float* __restrict__ W1,
             const float* __restrict__ b1, float* __restrict__ C1,
             const float* __restrict__ A2, const float* __restrict__ W2,
             const float* __restrict__ b2, float* __restrict__ C2)
{
    extern __shared__ __align__(16) float smem_dyn[];

    const float* A    = A0;
    const float* W    = W0;
    const float* bias = b0;
    float*       C    = C0;
    if (QKV) {
        const int z = blockIdx.z;
        if (z == 1) { A = A1; W = W1; bias = b1; C = C1; }
        else if (z == 2) { A = A2; W = W2; bias = b2; C = C2; }
    }

    const int tid  = threadIdx.x;
    const int lane = tid & 31, wid = tid >> 5;
    const int wm   = wid >> 2, wn = wid & 3;
    const int g    = lane >> 2, t = lane & 3;
    const int bm   = blockIdx.y * 128, bn = blockIdx.x * 128;

    const int arow = lane & 15;
    const int acol = (lane >> 4) * 4;
    const int brow = ((lane >> 4) << 3) + (lane & 7);
    const int bcol = ((lane >> 3) & 1) * 4;

    const uint32_t base = (uint32_t)__cvta_generic_to_shared(smem_dyn);
    const uint32_t STAGE_B = 20480u;            // bytes per stage (As+Ws)
    const uint32_t WS_OFF  = 10240u;            // Ws offset within stage

    const int crow = tid >> 2;
    const int csc  = (tid & 3) * 4;
    const float* Arow0 = A + (size_t)(bm + crow     ) * DMODEL + csc;
    const float* Arow1 = A + (size_t)(bm + crow + 64) * DMODEL + csc;
    const float* Wrow0 = W + (size_t)(bn + crow     ) * DMODEL + csc;
    const float* Wrow1 = W + (size_t)(bn + crow + 64) * DMODEL + csc;
    const uint32_t Ad0 = base + (uint32_t)((crow      * 20 + csc) * 4);
    const uint32_t Ad1 = base + (uint32_t)(((crow+64) * 20 + csc) * 4);
    const uint32_t Wd0 = Ad0 + WS_OFF;
    const uint32_t Wd1 = Ad1 + WS_OFF;

#define GEMM_ISSUE(st, k0)                                   \
    do {                                                     \
        const uint32_t so = (uint32_t)(st) * STAGE_B;        \
        cpasync16(Ad0 + so, Arow0 + (k0));                   \
        cpasync16(Ad1 + so, Arow1 + (k0));                   \
        cpasync16(Wd0 + so, Wrow0 + (k0));                   \
        cpasync16(Wd1 + so, Wrow1 + (k0));                   \
        cp_commit();                                         \
    } while (0)

    // prologue: stages 0 and 1 in flight
    GEMM_ISSUE(0, 0);
    GEMM_ISSUE(1, 16);
    cp_wait<1>();          // stage 0 ready
    __syncthreads();

    float acc[4][4][4] = {};
    const int NI = DMODEL / 16;   // 64

    for (int i = 0; i < NI; ++i) {
        const int cur = i % 3;
        // issue for i+2 into stage (i+2)%3 == (i-1)%3 or unused stage 2 at i=0;
        // that stage was fully drained before the barrier that ended iter i-1.
        if (i + 2 < NI) GEMM_ISSUE((i + 2) % 3, (i + 2) * 16);

        const uint32_t Asb = base + (uint32_t)cur * STAGE_B;
        const uint32_t Wsb = Asb + WS_OFF;

#pragma unroll
        for (int ks = 0; ks < 2; ++ks) {
            const int kb = ks * 8;
            uint32_t af[4][4], bf[4][2];
#pragma unroll
            for (int mt = 0; mt < 4; ++mt)
                ldsm4(af[mt], Asb + (uint32_t)(((wm*64 + mt*16 + arow)*20 + kb + acol) * 4));
#pragma unroll
            for (int p = 0; p < 2; ++p) {
                uint32_t r[4];
                ldsm4(r, Wsb + (uint32_t)(((wn*32 + p*16 + brow)*20 + kb + bcol) * 4));
                bf[p*2  ][0] = r[0]; bf[p*2  ][1] = r[1];
                bf[p*2+1][0] = r[2]; bf[p*2+1][1] = r[3];
            }
#pragma unroll
            for (int mt = 0; mt < 4; ++mt)
#pragma unroll
                for (int nt = 0; nt < 4; ++nt)
                    mma8(acc[mt][nt], af[mt], bf[nt]);
        }

        if (i + 2 < NI) cp_wait<1>();   // stage for i+1 complete
        else            cp_wait<0>();
        __syncthreads();                // visibility + drains stage cur
    }
#undef GEMM_ISSUE

    // epilogue
    const bool vtrans = QKV && (blockIdx.z == 2);
#pragma unroll
    for (int mt = 0; mt < 4; ++mt) {
        const int r0 = bm + wm*64 + mt*16 + g;
#pragma unroll
        for (int nt = 0; nt < 4; ++nt) {
            const int c0 = bn + wn*32 + nt*8 + t*2;
            const float bb0 = bias[c0], bb1 = bias[c0 + 1];
            float v00 = acc[mt][nt][0] + bb0, v01 = acc[mt][nt][1] + bb1;
            float v10 = acc[mt][nt][2] + bb0, v11 = acc[mt][nt][3] + bb1;
            if (SPLIT) {
                v00 = to_tf32(v00); v01 = to_tf32(v01);
                v10 = to_tf32(v10); v11 = to_tf32(v11);
                const int bb = r0 >> 11;
                const int s  = r0 & (SEQ - 1);
                const int h  = c0 >> 6;
                const int d  = c0 & 63;
                if (vtrans) {
                    float* bptr = C + (((size_t)(bb*NH + h))*DEPTH + d)*SEQ + s;
                    bptr[0]       = v00;  bptr[SEQ]     = v01;
                    bptr[8]       = v10;  bptr[SEQ + 8] = v11;
                } else {
                    float* p0 = C + (((size_t)(bb*NH + h))*SEQ + s    )*DEPTH + d;
                    float* p1 = C + (((size_t)(bb*NH + h))*SEQ + s + 8)*DEPTH + d;
                    *(float2*)p0 = make_float2(v00, v01);
                    *(float2*)p1 = make_float2(v10, v11);
                }
            } else {
                *(float2*)(C + (size_t)r0      * DMODEL + c0) = make_float2(v00, v01);
                *(float2*)(C + (size_t)(r0+8)  * DMODEL + c0) = make_float2(v10, v11);
            }
        }
    }
}

// ---------------------------------------------------------------------------
// Flash attention, tf32 tensor cores, cp.async K/V pipeline.
// (unchanged from round 15 — Q/K/V pre-rounded, V pre-transposed)
// ---------------------------------------------------------------------------
__global__ __launch_bounds__(128, 4)
void attn_tc(const float* __restrict__ Qh, const float* __restrict__ Kh,
             const float* __restrict__ VhT, const float* __restrict__ mask,
             float* __restrict__ Oc)
{
    __shared__ __align__(16) float Ks[2][32][68];
    __shared__ __align__(16) float Vt[2][64][36];
    __shared__ __align__(16) float Ps[64][36];

    const int tid  = threadIdx.x;
    const int lane = tid & 31, w = tid >> 5;
    const int g    = lane >> 2, t = lane & 3;
    const int bh   = blockIdx.x;         // b*NH + h
    const int qt   = blockIdx.y;
    const int b    = bh >> 4, h = bh & 15;

    const int arow = lane & 15;
    const int acol = (lane >> 4) * 4;
    const int brow = ((lane >> 4) << 3) + (lane & 7);
    const int bcol = ((lane >> 3) & 1) * 4;

    const uint32_t Ks_s = (uint32_t)__cvta_generic_to_shared(&Ks[0][0][0]);
    const uint32_t Vt_s = (uint32_t)__cvta_generic_to_shared(&Vt[0][0][0]);
    const uint32_t Ps_s = (uint32_t)__cvta_generic_to_shared(&Ps[0][0]);
    const uint32_t KSTAGE = 32u*68u*4u;
    const uint32_t VSTAGE = 64u*36u*4u;

    const float* Qb    = Qh + ((size_t)bh * SEQ + qt*64) * DEPTH;
    const float* qrow0 = Qb + (w*16 + g    ) * DEPTH;
    const float* qrow1 = Qb + (w*16 + g + 8) * DEPTH;
    uint32_t qf[8][4];
#pragma unroll
    for (int kb8 = 0; kb8 < 8; ++kb8) {
        qf[kb8][0] = __float_as_uint(__ldg(qrow0 + kb8*8 + t));
        qf[kb8][1] = __float_as_uint(__ldg(qrow1 + kb8*8 + t));
        qf[kb8][2] = __float_as_uint(__ldg(qrow0 + kb8*8 + t + 4));
        qf[kb8][3] = __float_as_uint(__ldg(qrow1 + kb8*8 + t + 4));
    }

    const float* Kb0 = Kh  + (size_t)bh * SEQ * DEPTH;
    const float* Vb0 = VhT + (size_t)bh * DEPTH * SEQ;
    const float* Mb  = mask + ((size_t)b * SEQ + qt*64) * SEQ;
    const int pr = w*16 + g;

    const int krow = tid >> 2, kcb = (tid & 3) * 16;
    const int vrow = tid >> 1, vcb = (tid & 1) * 16;
    const float* Kp = Kb0 + (size_t)krow * DEPTH + kcb;
    const float* Vp = Vb0 + (size_t)vrow * SEQ + vcb;
    const uint32_t Kd = Ks_s + (uint32_t)((krow*68 + kcb) * 4);
    const uint32_t Vd = Vt_s + (uint32_t)((vrow*36 + vcb) * 4);

#define ATTN_ISSUE(st, ktc)                                          \
    do {                                                             \
        const float* kp = Kp + (size_t)(ktc) * 32 * DEPTH;           \
        const float* vp = Vp + (ktc) * 32;                           \
        const uint32_t kd = Kd + (st) * KSTAGE;                      \
        const uint32_t vd = Vd + (st) * VSTAGE;                      \
        cpasync16(kd,      kp);      cpasync16(kd + 16, kp + 4);     \
        cpasync16(kd + 32, kp + 8);  cpasync16(kd + 48, kp + 12);    \
        cpasync16(vd,      vp);      cpasync16(vd + 16, vp + 4);     \
        cpasync16(vd + 32, vp + 8);  cpasync16(vd + 48, vp + 12);    \
        cp_commit();                                                 \
    } while (0)

    ATTN_ISSUE(0, 0);
    ATTN_ISSUE(1, 1);
    cp_wait<1>();
    __syncthreads();

    float oacc[8][4] = {};
    float m0 = -INFINITY, m1 = -INFINITY, l0 = 0.f, l1 = 0.f;

    for (int kt = 0; kt < NT; ++kt) {
        const int cur = kt & 1;
        const uint32_t Ksb = Ks_s + (uint32_t)cur * KSTAGE;
        const uint32_t Vtb = Vt_s + (uint32_t)cur * VSTAGE;

        float sacc[4][4] = {};
#pragma unroll
        for (int ks = 0; ks < 8; ++ks) {
            const int kb = ks * 8;
            uint32_t bf[4][2];
#pragma unroll
            for (int p = 0; p < 2; ++p) {
                uint32_t r[4];
                ldsm4(r, Ksb + (uint32_t)(((p*16 + brow)*68 + kb + bcol) * 4));
                bf[p*2  ][0] = r[0]; bf[p*2  ][1] = r[1];
                bf[p*2+1][0] = r[2]; bf[p*2+1][1] = r[3];
            }
#pragma unroll
            for (int nt = 0; nt < 4; ++nt)
                mma8(sacc[nt], qf[ks], bf[nt]);
        }

#pragma unroll
        for (int nt = 0; nt < 4; ++nt) {
            const int c0 = kt*32 + nt*8 + t*2;
            float2 mlo = *(const float2*)(Mb + (size_t)(w*16 + g    )*SEQ + c0);
            float2 mhi = *(const float2*)(Mb + (size_t)(w*16 + g + 8)*SEQ + c0);
            sacc[nt][0] = fmaf(mlo.x, -1e9f, sacc[nt][0]*0.125f);
            sacc[nt][1] = fmaf(mlo.y, -1e9f, sacc[nt][1]*0.125f);
            sacc[nt][2] = fmaf(mhi.x, -1e9f, sacc[nt][2]*0.125f);
            sacc[nt][3] = fmaf(mhi.y, -1e9f, sacc[nt][3]*0.125f);
        }

        float rm0 = -INFINITY, rm1 = -INFINITY;
#pragma unroll
        for (int nt = 0; nt < 4; ++nt) {
            rm0 = fmaxf(rm0, fmaxf(sacc[nt][0], sacc[nt][1]));
            rm1 = fmaxf(rm1, fmaxf(sacc[nt][2], sacc[nt][3]));
        }
        rm0 = fmaxf(rm0, __shfl_xor_sync(0xffffffffu, rm0, 1));
        rm0 = fmaxf(rm0, __shfl_xor_sync(0xffffffffu, rm0, 2));
        rm1 = fmaxf(rm1, __shfl_xor_sync(0xffffffffu, rm1, 1));
        rm1 = fmaxf(rm1, __shfl_xor_sync(0xffffffffu, rm1, 2));

        const float mn0 = fmaxf(m0, rm0), mn1 = fmaxf(m1, rm1);
        const float a0  = __expf(m0 - mn0), a1 = __expf(m1 - mn1);
        m0 = mn0; m1 = mn1;

        float sum0 = 0.f, sum1 = 0.f;
#pragma unroll
        for (int nt = 0; nt < 4; ++nt) {
            sacc[nt][0] = __expf(sacc[nt][0] - mn0); sum0 += sacc[nt][0];
            sacc[nt][1] = __expf(sacc[nt][1] - mn0); sum0 += sacc[nt][1];
            sacc[nt][2] = __expf(sacc[nt][2] - mn1); sum1 += sacc[nt][2];
            sacc[nt][3] = __expf(sacc[nt][3] - mn1); sum1 += sacc[nt][3];
        }
        sum0 += __shfl_xor_sync(0xffffffffu, sum0, 1);
        sum0 += __shfl_xor_sync(0xffffffffu, sum0, 2);
        sum1 += __shfl_xor_sync(0xffffffffu, sum1, 1);
        sum1 += __shfl_xor_sync(0xffffffffu, sum1, 2);
        l0 = l0*a0 + sum0;
        l1 = l1*a1 + sum1;
#pragma unroll
        for (int nt = 0; nt < 8; ++nt) {
            oacc[nt][0] *= a0; oacc[nt][1] *= a0;
            oacc[nt][2] *= a1; oacc[nt][3] *= a1;
        }

#pragma unroll
        for (int nt = 0; nt < 4; ++nt) {
            *(float2*)&Ps[pr    ][nt*8 + t*2] = make_float2(to_tf32(sacc[nt][0]), to_tf32(sacc[nt][1]));
            *(float2*)&Ps[pr + 8][nt*8 + t*2] = make_float2(to_tf32(sacc[nt][2]), to_tf32(sacc[nt][3]));
        }
        __syncwarp();

#pragma unroll
        for (int ks = 0; ks < 4; ++ks) {
            const int kb = ks * 8;
            uint32_t af[4];
            ldsm4(af, Ps_s + (uint32_t)(((w*16 + arow)*36 + kb + acol) * 4));
            uint32_t bf[8][2];
#pragma unroll
            for (int p = 0; p < 4; ++p) {
                uint32_t r[4];
                ldsm4(r, Vtb + (uint32_t)(((p*16 + brow)*36 + kb + bcol) * 4));
                bf[p*2  ][0] = r[0]; bf[p*2  ][1] = r[1];
                bf[p*2+1][0] = r[2]; bf[p*2+1][1] = r[3];
            }
#pragma unroll
            for (int nt = 0; nt < 8; ++nt)
                mma8(oacc[nt], af, bf[nt]);
        }

        __syncthreads();
        if (kt + 2 < NT) {
            ATTN_ISSUE(cur, kt + 2);
            cp_wait<1>();
        } else {
            cp_wait<0>();
        }
        __syncthreads();
    }
#undef ATTN_ISSUE

    const float inv0 = 1.f / l0, inv1 = 1.f / l1;
    const size_t row0 = (size_t)b*SEQ + qt*64 + w*16 + g;
#pragma unroll
    for (int nt = 0; nt < 8; ++nt) {
        const int c = h*64 + nt*8 + t*2;
        *(float2*)(Oc + row0     * DMODEL + c) =
            make_float2(to_tf32(oacc[nt][0]*inv0), to_tf32(oacc[nt][1]*inv0));
        *(float2*)(Oc + (row0+8) * DMODEL + c) =
            make_float2(to_tf32(oacc[nt][2]*inv1), to_tf32(oacc[nt][3]*inv1));
    }
}

// ---------------------------------------------------------------------------
extern "C" void kernel_launch(void* const* d_in, const int* in_sizes, int n_in,
                              void* d_out, int out_size)
{
    const float* v    = (const float*)d_in[0];
    const float* k    = (const float*)d_in[1];
    const float* q    = (const float*)d_in[2];
    const float* mask = (const float*)d_in[3];
    const float* wq   = (const float*)d_in[4];
    const float* bq   = (const float*)d_in[5];
    const float* wk   = (const float*)d_in[6];
    const float* bk   = (const float*)d_in[7];
    const float* wv   = (const float*)d_in[8];
    const float* bv   = (const float*)d_in[9];
    const float* wo   = (const float*)d_in[10];
    const float* bo   = (const float*)d_in[11];
    float* out = (float*)d_out;

    float *Qh, *Kh, *VhT, *Oc, *Qr, *Kr, *Vr, *Wq, *Wk, *Wv, *Wo;
    cudaGetSymbolAddress((void**)&Qh,  g_Qh);
    cudaGetSymbolAddress((void**)&Kh,  g_Kh);
    cudaGetSymbolAddress((void**)&VhT, g_VhT);
    cudaGetSymbolAddress((void**)&Oc,  g_Oc);
    cudaGetSymbolAddress((void**)&Qr,  g_Qr);
    cudaGetSymbolAddress((void**)&Kr,  g_Kr);
    cudaGetSymbolAddress((void**)&Vr,  g_Vr);
    cudaGetSymbolAddress((void**)&Wq,  g_Wq);
    cudaGetSymbolAddress((void**)&Wk,  g_Wk);
    cudaGetSymbolAddress((void**)&Wv,  g_Wv);
    cudaGetSymbolAddress((void**)&Wo,  g_Wo);

    const int SMEM_GEMM = 61440;   // 3 stages x 20480 B
    cudaFuncSetAttribute(gemm_tc<true, true>,
                         cudaFuncAttributeMaxDynamicSharedMemorySize, SMEM_GEMM);
    cudaFuncSetAttribute(gemm_tc<false, false>,
                         cudaFuncAttributeMaxDynamicSharedMemorySize, SMEM_GEMM);

    // pre-round all GEMM operands to tf32 (one-time, ~68 MB traffic)
    prep_round<<<16384, 256>>>((const float4*)q, (const float4*)k, (const float4*)v,
                               (const float4*)wq, (const float4*)wk,
                               (const float4*)wv, (const float4*)wo,
                               (float4*)Qr, (float4*)Kr, (float4*)Vr,
                               (float4*)Wq, (float4*)Wk, (float4*)Wv, (float4*)Wo);

    // fused Q/K/V projections
    dim3 gqkv(DMODEL/128, MROWS/128, 3);  // (8, 32, 3)
    gemm_tc<true, true><<<gqkv, 256, SMEM_GEMM>>>(Qr, Wq, bq, Qh,
                                                  Kr, Wk, bk, Kh,
                                                  Vr, Wv, bv, VhT);

    dim3 ga(BATCH*NH, SEQ/64);            // (32, 32)
    attn_tc<<<ga, 128>>>(Qh, Kh, VhT, mask, Oc);

    dim3 gg(DMODEL/128, MROWS/128);       // (8, 32)
    gemm_tc<false, false><<<gg, 256, SMEM_GEMM>>>(Oc, Wo, bo, out,
                                                  nullptr, nullptr, nullptr, nullptr,
                                                  nullptr, nullptr, nullptr, nullptr);
}